// round 3
// baseline (speedup 1.0000x reference)
#include <cuda_runtime.h>
#include <cstdint>

// ============================================================================
// InteractionBlock (DimeNet-like), FP32 baseline.
// H = 128 fixed. E (edges) and T (triplets) taken from in_sizes.
// ============================================================================

#define MAX_E 50000
#define MAX_T 200000

// Scratch (static __device__ arrays -- no allocation allowed)
__device__ float g_rbfh[MAX_E * 128];
__device__ float g_xkj [MAX_E * 128];
__device__ float g_h   [MAX_E * 128];
__device__ float g_tmp [MAX_E * 128];
__device__ float g_sbfh[MAX_T * 8];
__device__ float g_Wt  [8 * 128 * 128];   // Wt[j][k][n] = Wbil[n][j][k]

__device__ __forceinline__ float silu_f(float v) {
    return v / (1.0f + __expf(-v));
}

// ---------------------------------------------------------------------------
// Wbil [128(out n), 8(j), 128(k)]  ->  g_Wt [8(j), 128(k), 128(n)]
// ---------------------------------------------------------------------------
__global__ void transpose_wbil(const float* __restrict__ Wbil) {
    int gid = blockIdx.x * blockDim.x + threadIdx.x;
    if (gid >= 8 * 128 * 128) return;
    int n = gid & 127;
    int k = (gid >> 7) & 127;
    int j = gid >> 14;
    g_Wt[gid] = Wbil[n * 1024 + j * 128 + k];
}

// ---------------------------------------------------------------------------
// rbf_h[e,n] = sum_i rbf[e,i] * W_rbf[i,n]   (NR = 6)
// ---------------------------------------------------------------------------
__global__ void rbfh_kernel(const float* __restrict__ rbf,
                            const float* __restrict__ Wrbf, int E) {
    int gid = blockIdx.x * blockDim.x + threadIdx.x;
    if (gid >= E * 128) return;
    int e = gid >> 7, n = gid & 127;
    float acc = 0.0f;
#pragma unroll
    for (int i = 0; i < 6; i++) acc += rbf[e * 6 + i] * Wrbf[i * 128 + n];
    g_rbfh[gid] = acc;
}

// ---------------------------------------------------------------------------
// sbf_h[t,j] = sum_i sbf[t,i] * W_sbf[i,j]   (42 -> 8)
// ---------------------------------------------------------------------------
__global__ void sbfh_kernel(const float* __restrict__ sbf,
                            const float* __restrict__ Wsbf, int T) {
    int t = blockIdx.x * blockDim.x + threadIdx.x;
    if (t >= T) return;
    float acc[8];
#pragma unroll
    for (int j = 0; j < 8; j++) acc[j] = 0.0f;
    const float* row = sbf + (long)t * 42;
#pragma unroll
    for (int i = 0; i < 42; i++) {
        float s = row[i];
#pragma unroll
        for (int j = 0; j < 8; j++) acc[j] += s * Wsbf[i * 8 + j];
    }
    float4* o = (float4*)(g_sbfh + t * 8);
    o[0] = make_float4(acc[0], acc[1], acc[2], acc[3]);
    o[1] = make_float4(acc[4], acc[5], acc[6], acc[7]);
}

// ---------------------------------------------------------------------------
// Generic C[M,128] = epilogue( A[M,128] @ W[128,128] + bias )
// EP = 0 : C = silu(.)
// EP = 1 : C = silu(.) * extra[row]
// EP = 2 : C = silu(.) + extra[row]
// BM=64, BN=128, K=128 resident in smem. 128 threads, 8x8 microtiles.
// ---------------------------------------------------------------------------
template <int EP>
__global__ void gemm128(const float* __restrict__ A, const float* __restrict__ W,
                        const float* __restrict__ bias,
                        const float* __restrict__ extra,
                        float* __restrict__ C, int M) {
    extern __shared__ float sm[];
    float* As = sm;             // 64 * 129 (padded, conflict-free)
    float* Ws = sm + 64 * 129;  // 128 * 128

    const int tid  = threadIdx.x;
    const int brow = blockIdx.x * 64;

    {   // load W tile (64 KB)
        const float4* Wg  = (const float4*)W;
        float4*       Wsh = (float4*)Ws;
#pragma unroll
        for (int i = 0; i < 32; i++) Wsh[i * 128 + tid] = Wg[i * 128 + tid];
    }
    {   // load A tile (guarded, transposed-store into padded rows)
        const float4* Ag = (const float4*)A;
#pragma unroll
        for (int it = 0; it < 16; it++) {
            int i  = it * 128 + tid;
            int r  = i >> 5, c4 = i & 31;
            int row = brow + r;
            float4 v = make_float4(0.f, 0.f, 0.f, 0.f);
            if (row < M) v = Ag[row * 32 + c4];
            float* dst = As + r * 129 + c4 * 4;
            dst[0] = v.x; dst[1] = v.y; dst[2] = v.z; dst[3] = v.w;
        }
    }
    __syncthreads();

    const int tmg = tid >> 4;   // 8 row groups of 8
    const int tng = tid & 15;   // 16 col groups of 8
    const float*  Ab  = As + tmg * 8 * 129;
    const float4* Ws4 = (const float4*)Ws;

    float acc[8][8];
#pragma unroll
    for (int i = 0; i < 8; i++)
#pragma unroll
        for (int j = 0; j < 8; j++) acc[i][j] = 0.0f;

#pragma unroll 4
    for (int k = 0; k < 128; k++) {
        float a[8];
#pragma unroll
        for (int i = 0; i < 8; i++) a[i] = Ab[i * 129 + k];
        float4 b0 = Ws4[k * 32 + tng * 2];
        float4 b1 = Ws4[k * 32 + tng * 2 + 1];
        float b[8] = {b0.x, b0.y, b0.z, b0.w, b1.x, b1.y, b1.z, b1.w};
#pragma unroll
        for (int i = 0; i < 8; i++)
#pragma unroll
            for (int j = 0; j < 8; j++) acc[i][j] += a[i] * b[j];
    }

    float bc[8];
#pragma unroll
    for (int j = 0; j < 8; j++) bc[j] = bias[tng * 8 + j];

#pragma unroll
    for (int i = 0; i < 8; i++) {
        int row = brow + tmg * 8 + i;
        if (row >= M) continue;
        float ex[8];
        if (EP == 1 || EP == 2) {
            float4 e0 = ((const float4*)extra)[row * 32 + tng * 2];
            float4 e1 = ((const float4*)extra)[row * 32 + tng * 2 + 1];
            ex[0] = e0.x; ex[1] = e0.y; ex[2] = e0.z; ex[3] = e0.w;
            ex[4] = e1.x; ex[5] = e1.y; ex[6] = e1.z; ex[7] = e1.w;
        }
        float o[8];
#pragma unroll
        for (int j = 0; j < 8; j++) {
            float v = silu_f(acc[i][j] + bc[j]);
            if (EP == 1) v *= ex[j];
            if (EP == 2) v += ex[j];
            o[j] = v;
        }
        float4* Cp = (float4*)C;
        Cp[row * 32 + tng * 2]     = make_float4(o[0], o[1], o[2], o[3]);
        Cp[row * 32 + tng * 2 + 1] = make_float4(o[4], o[5], o[6], o[7]);
    }
}

// ---------------------------------------------------------------------------
// Bilinear + scatter:
//   msg[t,n] = sum_j sbf_h[t,j] * sum_k x_kj[idx_kj[t],k] * Wt[j][k][n]
//   agg[idx_ji[t], n] += msg[t,n]   (float4 atomicAdd into g_h)
// BM = 64 triplets / block, 128 threads, 8x8 microtiles; loops j over the
// 8 Wbil slabs, folding the per-row sbf_h scale into the a-fragment.
// ---------------------------------------------------------------------------
__global__ void bilinear_kernel(const float* __restrict__ xkj,
                                const int* __restrict__ idx_kj,
                                const int* __restrict__ idx_ji,
                                float* __restrict__ agg, int T) {
    extern __shared__ float sm[];
    float* As = sm;                         // 64*129 = 8256
    float* Ws = sm + 8256;                  // 16384
    float* Ss = sm + 8256 + 16384;          // 64*8 = 512
    int*   Is = (int*)(sm + 8256 + 16384 + 512);  // 64

    const int tid = threadIdx.x;
    const int t0  = blockIdx.x * 64;

    {   // gather A rows via idx_kj (guarded)
        const float4* Xg = (const float4*)xkj;
#pragma unroll
        for (int it = 0; it < 16; it++) {
            int i  = it * 128 + tid;
            int r  = i >> 5, c4 = i & 31;
            int tt = t0 + r;
            float4 v = make_float4(0.f, 0.f, 0.f, 0.f);
            if (tt < T) {
                int src = idx_kj[tt];
                v = Xg[src * 32 + c4];
            }
            float* dst = As + r * 129 + c4 * 4;
            dst[0] = v.x; dst[1] = v.y; dst[2] = v.z; dst[3] = v.w;
        }
    }
    for (int i = tid; i < 512; i += 128) {
        int tt = t0 + (i >> 3);
        Ss[i] = (tt < T) ? g_sbfh[tt * 8 + (i & 7)] : 0.0f;
    }
    if (tid < 64) {
        int tt = t0 + tid;
        Is[tid] = (tt < T) ? idx_ji[tt] : 0;
    }

    const int tmg = tid >> 4;
    const int tng = tid & 15;
    const float*  Ab  = As + tmg * 8 * 129;
    const float4* Ws4 = (const float4*)Ws;

    float acc[8][8];
#pragma unroll
    for (int i = 0; i < 8; i++)
#pragma unroll
        for (int j = 0; j < 8; j++) acc[i][j] = 0.0f;

    for (int j = 0; j < 8; j++) {
        __syncthreads();   // protects As/Ss/Is on j=0, Ws reuse afterwards
        const float4* Wg  = (const float4*)(g_Wt + j * 16384);
        float4*       Wsh = (float4*)Ws;
#pragma unroll
        for (int i = 0; i < 32; i++) Wsh[i * 128 + tid] = Wg[i * 128 + tid];
        __syncthreads();

        float sf[8];
#pragma unroll
        for (int i = 0; i < 8; i++) sf[i] = Ss[(tmg * 8 + i) * 8 + j];

#pragma unroll 4
        for (int k = 0; k < 128; k++) {
            float a[8];
#pragma unroll
            for (int i = 0; i < 8; i++) a[i] = Ab[i * 129 + k] * sf[i];
            float4 b0 = Ws4[k * 32 + tng * 2];
            float4 b1 = Ws4[k * 32 + tng * 2 + 1];
            float b[8] = {b0.x, b0.y, b0.z, b0.w, b1.x, b1.y, b1.z, b1.w};
#pragma unroll
            for (int i = 0; i < 8; i++)
#pragma unroll
                for (int jj = 0; jj < 8; jj++) acc[i][jj] += a[i] * b[jj];
        }
    }

    // scatter-add into agg (g_h already holds x_ji)
#pragma unroll
    for (int i = 0; i < 8; i++) {
        int tt = t0 + tmg * 8 + i;
        if (tt >= T) continue;
        int e = Is[tmg * 8 + i];
        float4* p = (float4*)(agg + e * 128 + tng * 8);
        atomicAdd(p,     make_float4(acc[i][0], acc[i][1], acc[i][2], acc[i][3]));
        atomicAdd(p + 1, make_float4(acc[i][4], acc[i][5], acc[i][6], acc[i][7]));
    }
}

// ---------------------------------------------------------------------------
// Host launcher
// ---------------------------------------------------------------------------
extern "C" void kernel_launch(void* const* d_in, const int* in_sizes, int n_in,
                              void* d_out, int out_size) {
    const float* x      = (const float*)d_in[0];
    const float* rbf    = (const float*)d_in[1];
    const float* sbf    = (const float*)d_in[2];
    const int*   idx_kj = (const int*)d_in[3];
    const int*   idx_ji = (const int*)d_in[4];
    const float* W_rbf  = (const float*)d_in[5];
    const float* W_sbf  = (const float*)d_in[6];
    const float* Wkj    = (const float*)d_in[7];
    const float* bkj    = (const float*)d_in[8];
    const float* Wji    = (const float*)d_in[9];
    const float* bji    = (const float*)d_in[10];
    const float* Wbil   = (const float*)d_in[11];
    const float* bW1    = (const float*)d_in[12];
    const float* bb1    = (const float*)d_in[13];
    const float* bW2    = (const float*)d_in[14];
    const float* bb2    = (const float*)d_in[15];
    const float* Wlin   = (const float*)d_in[16];
    const float* blin   = (const float*)d_in[17];
    const float* aW1    = (const float*)d_in[18];
    const float* ab1    = (const float*)d_in[19];
    const float* aW2    = (const float*)d_in[20];
    const float* ab2    = (const float*)d_in[21];
    const float* Wout   = (const float*)d_in[22];
    const float* bout   = (const float*)d_in[23];
    float* out = (float*)d_out;

    const int E = in_sizes[0] / 128;
    const int T = in_sizes[3];

    float *rbfh, *xkj, *h, *tmp;
    cudaGetSymbolAddress((void**)&rbfh, g_rbfh);
    cudaGetSymbolAddress((void**)&xkj,  g_xkj);
    cudaGetSymbolAddress((void**)&h,    g_h);
    cudaGetSymbolAddress((void**)&tmp,  g_tmp);

    const size_t gsm = (size_t)(64 * 129 + 128 * 128) * sizeof(float);
    const size_t bsm = (size_t)(64 * 129 + 128 * 128 + 512 + 64) * sizeof(float);
    cudaFuncSetAttribute(gemm128<0>, cudaFuncAttributeMaxDynamicSharedMemorySize, (int)gsm);
    cudaFuncSetAttribute(gemm128<1>, cudaFuncAttributeMaxDynamicSharedMemorySize, (int)gsm);
    cudaFuncSetAttribute(gemm128<2>, cudaFuncAttributeMaxDynamicSharedMemorySize, (int)gsm);
    cudaFuncSetAttribute(bilinear_kernel, cudaFuncAttributeMaxDynamicSharedMemorySize, (int)bsm);

    // Stage 0: tiny preps
    transpose_wbil<<<(8 * 128 * 128 + 255) / 256, 256>>>(Wbil);
    rbfh_kernel<<<(E * 128 + 255) / 256, 256>>>(rbf, W_rbf, E);
    sbfh_kernel<<<(T + 255) / 256, 256>>>(sbf, W_sbf, T);

    const int gE = (E + 63) / 64;
    const int gT = (T + 63) / 64;

    // Stage A: x_ji -> g_h (acts as agg init), x_kj -> g_xkj
    gemm128<0><<<gE, 128, gsm>>>(x, Wji, bji, nullptr, h, E);
    gemm128<1><<<gE, 128, gsm>>>(x, Wkj, bkj, rbfh, xkj, E);

    // Stage B: bilinear + scatter into g_h  => h = x_ji + agg
    bilinear_kernel<<<gT, 128, bsm>>>(xkj, idx_kj, idx_ji, h, T);

    // Stage C: before-skip MLP (1x):  h += silu(silu(h@W1+b1)@W2+b2)
    gemm128<0><<<gE, 128, gsm>>>(h,   bW1, bb1, nullptr, tmp, E);
    gemm128<2><<<gE, 128, gsm>>>(tmp, bW2, bb2, h,       h,   E);

    // Stage D: h = silu(h@Wlin+blin) + x
    gemm128<2><<<gE, 128, gsm>>>(h, Wlin, blin, x, h, E);

    // Stage E: after-skip MLP (2x)
    for (int i = 0; i < 2; i++) {
        gemm128<0><<<gE, 128, gsm>>>(h,   aW1 + i * 16384, ab1 + i * 128, nullptr, tmp, E);
        gemm128<2><<<gE, 128, gsm>>>(tmp, aW2 + i * 16384, ab2 + i * 128, h,       h,   E);
    }

    // Stage F: out = silu(h @ Wout + bout)
    gemm128<0><<<gE, 128, gsm>>>(h, Wout, bout, nullptr, out, E);
}

// round 7
// speedup vs baseline: 1.9450x; 1.9450x over previous
#include <cuda_runtime.h>
#include <cstdint>
#include <cstddef>

// ============================================================================
// InteractionBlock (DimeNet-like), FP32. H = 128 fixed.
// Round 3: bilinear reassociated to per-EDGE precompute y[e,j,n] + per-triplet
// gather/weighted-sum/scatter. SGEMM core: full-K A in smem, cp.async
// double-buffered W chunks, float4-only smem reads, 4 blocks/SM.
// ============================================================================

#define MAX_E 50000
#define MAX_T 200000

__device__ float g_rbfh[MAX_E * 128];
__device__ float g_xkj [MAX_E * 128];
__device__ float g_h   [MAX_E * 128];
__device__ float g_tmp [MAX_E * 128];
__device__ float g_sbfh[MAX_T * 8];
__device__ float g_Wt  [8 * 128 * 128];     // Wt[j][k][n] = Wbil[n][j][k]
__device__ float g_y   [MAX_E * 1024];      // y[e][j*128+n]  (204.8 MB)

__device__ __forceinline__ float silu_f(float v) {
    return v / (1.0f + __expf(-v));
}

__device__ __forceinline__ void cp_async16(void* smem_dst, const void* gl_src) {
    uint32_t s = (uint32_t)__cvta_generic_to_shared(smem_dst);
    asm volatile("cp.async.cg.shared.global [%0], [%1], 16;\n" :: "r"(s), "l"(gl_src));
}
__device__ __forceinline__ void cp_async_commit() {
    asm volatile("cp.async.commit_group;\n" ::: "memory");
}
__device__ __forceinline__ void cp_async_wait0() {
    asm volatile("cp.async.wait_group 0;\n" ::: "memory");
}

// ---------------------------------------------------------------------------
// Tiny prep kernels
// ---------------------------------------------------------------------------
__global__ void transpose_wbil(const float* __restrict__ Wbil) {
    int gid = blockIdx.x * blockDim.x + threadIdx.x;
    if (gid >= 8 * 128 * 128) return;
    int n = gid & 127;
    int k = (gid >> 7) & 127;
    int j = gid >> 14;
    g_Wt[gid] = Wbil[n * 1024 + j * 128 + k];
}

__global__ void rbfh_kernel(const float* __restrict__ rbf,
                            const float* __restrict__ Wrbf, int E) {
    int gid = blockIdx.x * blockDim.x + threadIdx.x;
    if (gid >= E * 128) return;
    int e = gid >> 7, n = gid & 127;
    float acc = 0.0f;
#pragma unroll
    for (int i = 0; i < 6; i++) acc += rbf[e * 6 + i] * Wrbf[i * 128 + n];
    g_rbfh[gid] = acc;
}

__global__ void sbfh_kernel(const float* __restrict__ sbf,
                            const float* __restrict__ Wsbf, int T) {
    int t = blockIdx.x * blockDim.x + threadIdx.x;
    if (t >= T) return;
    float acc[8];
#pragma unroll
    for (int j = 0; j < 8; j++) acc[j] = 0.0f;
    const float* row = sbf + (long)t * 42;
#pragma unroll
    for (int i = 0; i < 42; i++) {
        float s = row[i];
#pragma unroll
        for (int j = 0; j < 8; j++) acc[j] += s * Wsbf[i * 8 + j];
    }
    float4* o = (float4*)(g_sbfh + t * 8);
    o[0] = make_float4(acc[0], acc[1], acc[2], acc[3]);
    o[1] = make_float4(acc[4], acc[5], acc[6], acc[7]);
}

// ---------------------------------------------------------------------------
// Shared inner compute: one BK=16 chunk.  As4: [64 rows][33 float4 stride],
// Wc4: [16 k][32 float4].  acc[8][8].
// ---------------------------------------------------------------------------
__device__ __forceinline__ void chunk_mma(const float4* __restrict__ As4,
                                          const float4* __restrict__ Wc4,
                                          int kt, int tmg, int tng,
                                          float acc[8][8]) {
#pragma unroll
    for (int k4 = 0; k4 < 4; k4++) {
        float4 b[4][2];
#pragma unroll
        for (int kk = 0; kk < 4; kk++) {
            b[kk][0] = Wc4[(k4 * 4 + kk) * 32 + tng * 2];
            b[kk][1] = Wc4[(k4 * 4 + kk) * 32 + tng * 2 + 1];
        }
#pragma unroll
        for (int i = 0; i < 8; i++) {
            float4 a = As4[(tmg * 8 + i) * 33 + kt * 4 + k4];
            float av[4] = {a.x, a.y, a.z, a.w};
#pragma unroll
            for (int kk = 0; kk < 4; kk++) {
                float f = av[kk];
                acc[i][0] += f * b[kk][0].x;
                acc[i][1] += f * b[kk][0].y;
                acc[i][2] += f * b[kk][0].z;
                acc[i][3] += f * b[kk][0].w;
                acc[i][4] += f * b[kk][1].x;
                acc[i][5] += f * b[kk][1].y;
                acc[i][6] += f * b[kk][1].z;
                acc[i][7] += f * b[kk][1].w;
            }
        }
    }
}

// smem: As 64*132 floats + Wbuf 2*16*128 floats = 50176 B
#define GEMM_SMEM ((64 * 132 + 2 * 16 * 128) * sizeof(float))

// ---------------------------------------------------------------------------
// Edge GEMM: C[M,128] = epilogue( A[M,128] @ W[128,128] + bias )
// EP = 0 : silu        EP = 1 : silu * extra[row]      EP = 2 : silu + extra[row]
// ---------------------------------------------------------------------------
template <int EP>
__global__ void __launch_bounds__(128, 4)
gemm_ek(const float* __restrict__ A, const float* __restrict__ W,
        const float* __restrict__ bias, const float* __restrict__ extra,
        float* __restrict__ C, int M) {
    extern __shared__ float sm[];
    float4* As4 = (float4*)sm;                    // 64 x 33 float4
    float4* Wb4 = (float4*)(sm + 64 * 132);       // 2 x 512 float4

    const int tid  = threadIdx.x;
    const int brow = blockIdx.x * 64;
    const float4* Ag = (const float4*)A;
    const float4* Wg = (const float4*)W;

    // full-K A tile (guarded)
#pragma unroll
    for (int it = 0; it < 16; it++) {
        int i = it * 128 + tid;
        int r = i >> 5, c4 = i & 31;
        float4 v = make_float4(0.f, 0.f, 0.f, 0.f);
        if (brow + r < M) v = Ag[(size_t)(brow + r) * 32 + c4];
        As4[r * 33 + c4] = v;
    }
    // W chunk 0 via cp.async
#pragma unroll
    for (int q = 0; q < 4; q++) {
        int i = q * 128 + tid;
        int wr = i >> 5, wc4 = i & 31;
        cp_async16(&Wb4[wr * 32 + wc4], &Wg[wr * 32 + wc4]);
    }
    cp_async_commit();
    cp_async_wait0();
    __syncthreads();

    const int tmg = tid >> 4;
    const int tng = tid & 15;

    float acc[8][8];
#pragma unroll
    for (int i = 0; i < 8; i++)
#pragma unroll
        for (int j = 0; j < 8; j++) acc[i][j] = 0.0f;

#pragma unroll 1
    for (int kt = 0; kt < 8; kt++) {
        if (kt < 7) {
            int nb = (kt + 1) & 1;
#pragma unroll
            for (int q = 0; q < 4; q++) {
                int i = q * 128 + tid;
                int wr = i >> 5, wc4 = i & 31;
                cp_async16(&Wb4[nb * 512 + wr * 32 + wc4],
                           &Wg[((kt + 1) * 16 + wr) * 32 + wc4]);
            }
            cp_async_commit();
        }
        chunk_mma(As4, Wb4 + (kt & 1) * 512, kt, tmg, tng, acc);
        if (kt < 7) {
            cp_async_wait0();
            __syncthreads();
        }
    }

    float bc[8];
#pragma unroll
    for (int j = 0; j < 8; j++) bc[j] = bias[tng * 8 + j];

#pragma unroll
    for (int i = 0; i < 8; i++) {
        int row = brow + tmg * 8 + i;
        if (row >= M) continue;
        float ex[8];
        if (EP == 1 || EP == 2) {
            float4 e0 = ((const float4*)extra)[(size_t)row * 32 + tng * 2];
            float4 e1 = ((const float4*)extra)[(size_t)row * 32 + tng * 2 + 1];
            ex[0] = e0.x; ex[1] = e0.y; ex[2] = e0.z; ex[3] = e0.w;
            ex[4] = e1.x; ex[5] = e1.y; ex[6] = e1.z; ex[7] = e1.w;
        }
        float o[8];
#pragma unroll
        for (int j = 0; j < 8; j++) {
            float v = silu_f(acc[i][j] + bc[j]);
            if (EP == 1) v *= ex[j];
            if (EP == 2) v += ex[j];
            o[j] = v;
        }
        float4* Cp = (float4*)C;
        Cp[(size_t)row * 32 + tng * 2]     = make_float4(o[0], o[1], o[2], o[3]);
        Cp[(size_t)row * 32 + tng * 2 + 1] = make_float4(o[4], o[5], o[6], o[7]);
    }
}

// ---------------------------------------------------------------------------
// y[e, j*128+n] = sum_k x_kj[e,k] * Wt[j,k,n].  A-tile loaded once, reused
// across the 8 j-slabs. No bias/activation.
// ---------------------------------------------------------------------------
__global__ void __launch_bounds__(128, 4)
ygemm(const float* __restrict__ Axkj, float* __restrict__ Y, int E) {
    extern __shared__ float sm[];
    float4* As4 = (float4*)sm;
    float4* Wb4 = (float4*)(sm + 64 * 132);

    const int tid  = threadIdx.x;
    const int brow = blockIdx.x * 64;
    const float4* Ag = (const float4*)Axkj;

#pragma unroll
    for (int it = 0; it < 16; it++) {
        int i = it * 128 + tid;
        int r = i >> 5, c4 = i & 31;
        float4 v = make_float4(0.f, 0.f, 0.f, 0.f);
        if (brow + r < E) v = Ag[(size_t)(brow + r) * 32 + c4];
        As4[r * 33 + c4] = v;
    }
    __syncthreads();

    const int tmg = tid >> 4;
    const int tng = tid & 15;
    float4* Y4 = (float4*)Y;

#pragma unroll 1
    for (int j = 0; j < 8; j++) {
        const float4* Wg = ((const float4*)g_Wt) + j * 4096;

        // chunk 0 prologue (safe: previous j's last chunk used the other buf,
        // and its read of buf0 was fenced by the kt=6 syncthreads)
#pragma unroll
        for (int q = 0; q < 4; q++) {
            int i = q * 128 + tid;
            int wr = i >> 5, wc4 = i & 31;
            cp_async16(&Wb4[wr * 32 + wc4], &Wg[wr * 32 + wc4]);
        }
        cp_async_commit();
        cp_async_wait0();
        __syncthreads();

        float acc[8][8];
#pragma unroll
        for (int i = 0; i < 8; i++)
#pragma unroll
            for (int jj = 0; jj < 8; jj++) acc[i][jj] = 0.0f;

#pragma unroll 1
        for (int kt = 0; kt < 8; kt++) {
            if (kt < 7) {
                int nb = (kt + 1) & 1;
#pragma unroll
                for (int q = 0; q < 4; q++) {
                    int i = q * 128 + tid;
                    int wr = i >> 5, wc4 = i & 31;
                    cp_async16(&Wb4[nb * 512 + wr * 32 + wc4],
                               &Wg[((kt + 1) * 16 + wr) * 32 + wc4]);
                }
                cp_async_commit();
            }
            chunk_mma(As4, Wb4 + (kt & 1) * 512, kt, tmg, tng, acc);
            if (kt < 7) {
                cp_async_wait0();
                __syncthreads();
            }
        }

        // write y slab j
#pragma unroll
        for (int i = 0; i < 8; i++) {
            int row = brow + tmg * 8 + i;
            if (row >= E) continue;
            size_t base = (size_t)row * 256 + j * 32 + tng * 2;
            Y4[base]     = make_float4(acc[i][0], acc[i][1], acc[i][2], acc[i][3]);
            Y4[base + 1] = make_float4(acc[i][4], acc[i][5], acc[i][6], acc[i][7]);
        }
        __syncthreads();   // all reads of Wb done before next j's prologue writes
    }
}

// ---------------------------------------------------------------------------
// Combine + scatter: one warp per triplet.
//   acc[n] = sum_j sbf_h[t,j] * y[idx_kj[t], j, n] ;  h[idx_ji[t], n] += acc[n]
// ---------------------------------------------------------------------------
__global__ void __launch_bounds__(256)
combine_kernel(const float* __restrict__ Y,
               const int* __restrict__ idx_kj, const int* __restrict__ idx_ji,
               float* __restrict__ h, int T) {
    int t = blockIdx.x * 8 + (threadIdx.x >> 5);
    if (t >= T) return;
    int lane = threadIdx.x & 31;

    int ekj = __ldg(&idx_kj[t]);
    int eji = __ldg(&idx_ji[t]);
    const float4* s4 = (const float4*)(g_sbfh + (size_t)t * 8);
    float4 sA = s4[0], sB = s4[1];
    float s[8] = {sA.x, sA.y, sA.z, sA.w, sB.x, sB.y, sB.z, sB.w};

    const float4* yr = (const float4*)(Y + (size_t)ekj * 1024);
    float4 acc = make_float4(0.f, 0.f, 0.f, 0.f);
#pragma unroll
    for (int j = 0; j < 8; j++) {
        float4 v = __ldg(&yr[j * 32 + lane]);
        acc.x += s[j] * v.x;
        acc.y += s[j] * v.y;
        acc.z += s[j] * v.z;
        acc.w += s[j] * v.w;
    }
    atomicAdd(&((float4*)h)[(size_t)eji * 32 + lane], acc);
}

// ---------------------------------------------------------------------------
// Host launcher
// ---------------------------------------------------------------------------
extern "C" void kernel_launch(void* const* d_in, const int* in_sizes, int n_in,
                              void* d_out, int out_size) {
    const float* x      = (const float*)d_in[0];
    const float* rbf    = (const float*)d_in[1];
    const float* sbf    = (const float*)d_in[2];
    const int*   idx_kj = (const int*)d_in[3];
    const int*   idx_ji = (const int*)d_in[4];
    const float* W_rbf  = (const float*)d_in[5];
    const float* W_sbf  = (const float*)d_in[6];
    const float* Wkj    = (const float*)d_in[7];
    const float* bkj    = (const float*)d_in[8];
    const float* Wji    = (const float*)d_in[9];
    const float* bji    = (const float*)d_in[10];
    const float* Wbil   = (const float*)d_in[11];
    const float* bW1    = (const float*)d_in[12];
    const float* bb1    = (const float*)d_in[13];
    const float* bW2    = (const float*)d_in[14];
    const float* bb2    = (const float*)d_in[15];
    const float* Wlin   = (const float*)d_in[16];
    const float* blin   = (const float*)d_in[17];
    const float* aW1    = (const float*)d_in[18];
    const float* ab1    = (const float*)d_in[19];
    const float* aW2    = (const float*)d_in[20];
    const float* ab2    = (const float*)d_in[21];
    const float* Wout   = (const float*)d_in[22];
    const float* bout   = (const float*)d_in[23];
    float* out = (float*)d_out;

    const int E = in_sizes[0] / 128;
    const int T = in_sizes[3];

    float *rbfh, *xkj, *h, *tmp, *y;
    cudaGetSymbolAddress((void**)&rbfh, g_rbfh);
    cudaGetSymbolAddress((void**)&xkj,  g_xkj);
    cudaGetSymbolAddress((void**)&h,    g_h);
    cudaGetSymbolAddress((void**)&tmp,  g_tmp);
    cudaGetSymbolAddress((void**)&y,    g_y);

    cudaFuncSetAttribute(gemm_ek<0>, cudaFuncAttributeMaxDynamicSharedMemorySize, (int)GEMM_SMEM);
    cudaFuncSetAttribute(gemm_ek<1>, cudaFuncAttributeMaxDynamicSharedMemorySize, (int)GEMM_SMEM);
    cudaFuncSetAttribute(gemm_ek<2>, cudaFuncAttributeMaxDynamicSharedMemorySize, (int)GEMM_SMEM);
    cudaFuncSetAttribute(ygemm,      cudaFuncAttributeMaxDynamicSharedMemorySize, (int)GEMM_SMEM);

    // Stage 0: tiny preps
    transpose_wbil<<<(8 * 128 * 128 + 255) / 256, 256>>>(Wbil);
    rbfh_kernel<<<(E * 128 + 255) / 256, 256>>>(rbf, W_rbf, E);
    sbfh_kernel<<<(T + 255) / 256, 256>>>(sbf, W_sbf, T);

    const int gE = (E + 63) / 64;

    // Stage A: x_ji -> g_h (doubles as agg init), x_kj -> g_xkj
    gemm_ek<0><<<gE, 128, GEMM_SMEM>>>(x, Wji, bji, nullptr, h, E);
    gemm_ek<1><<<gE, 128, GEMM_SMEM>>>(x, Wkj, bkj, rbfh, xkj, E);

    // Stage B1: per-edge bilinear precompute y[e,j,n]
    ygemm<<<gE, 128, GEMM_SMEM>>>(xkj, y, E);

    // Stage B2: per-triplet combine + scatter into h  => h = x_ji + agg
    combine_kernel<<<(T + 7) / 8, 256>>>(y, idx_kj, idx_ji, h, T);

    // Stage C: before-skip MLP (1x)
    gemm_ek<0><<<gE, 128, GEMM_SMEM>>>(h,   bW1, bb1, nullptr, tmp, E);
    gemm_ek<2><<<gE, 128, GEMM_SMEM>>>(tmp, bW2, bb2, h,       h,   E);

    // Stage D: h = silu(h@Wlin+blin) + x
    gemm_ek<2><<<gE, 128, GEMM_SMEM>>>(h, Wlin, blin, x, h, E);

    // Stage E: after-skip MLP (2x)
    for (int i = 0; i < 2; i++) {
        gemm_ek<0><<<gE, 128, GEMM_SMEM>>>(h,   aW1 + i * 16384, ab1 + i * 128, nullptr, tmp, E);
        gemm_ek<2><<<gE, 128, GEMM_SMEM>>>(tmp, aW2 + i * 16384, ab2 + i * 128, h,       h,   E);
    }

    // Stage F: out = silu(h @ Wout + bout)
    gemm_ek<0><<<gE, 128, GEMM_SMEM>>>(h, Wout, bout, nullptr, out, E);
}